// round 1
// baseline (speedup 1.0000x reference)
#include <cuda_runtime.h>
#include <cuda_bf16.h>
#include <math.h>

// Problem constants (fixed shapes)
#define NN    32768
#define EE    262144
#define HID   64
#define HEADS 4
#define CC    64
#define HC    256   // HEADS*CC
#define EDIM  3

// ---------------- scratch (device globals; no allocation allowed) ----------------
__device__ float    g_x[(size_t)NN * HC];      // projected features [N, H, C]
__device__ float    g_as[NN * HEADS];          // alpha_src per node/head
__device__ float    g_ad[NN * HEADS];          // alpha_dst per node/head
__device__ float    g_ex[(size_t)EE * HEADS];  // logit, then exp(logit-max), per edge/head
__device__ unsigned g_maxkey[NN * HEADS];      // segment max (ordered-uint encoded float)
__device__ float    g_denom[NN * HEADS];       // segment sum of exp
__device__ float    g_accum[(size_t)NN * CC];  // scatter-add output (head-combined)
__device__ float    g_z[(size_t)NN * HID];     // inter-layer activation
__device__ float    g_v[EDIM * HEADS];         // We-projected att_edge reduction [3,4]

// ---------------- helpers ----------------
__device__ __forceinline__ unsigned fenc(float f) {
    unsigned u = __float_as_uint(f);
    return (u & 0x80000000u) ? ~u : (u | 0x80000000u);
}
__device__ __forceinline__ float fdec(unsigned k) {
    unsigned u = (k & 0x80000000u) ? (k & 0x7FFFFFFFu) : ~k;
    return __uint_as_float(u);
}

// ---------------- init: reset per-layer accumulators ----------------
__global__ void k_init() {
    int i = blockIdx.x * blockDim.x + threadIdx.x;
    if (i < NN * HEADS) {
        g_maxkey[i] = 0x007FFFFFu;   // fenc(-inf)
        g_denom[i]  = 0.0f;
    }
    if (i < NN * CC) g_accum[i] = 0.0f;
}

// ---------------- v[d][h] = sum_c We[d, h*C+c] * a_edge[h,c] ----------------
__global__ void k_v(const float* __restrict__ We, const float* __restrict__ ae) {
    int t = threadIdx.x;
    if (t < EDIM * HEADS) {
        int d = t / HEADS, h = t % HEADS;
        float s = 0.f;
        for (int c = 0; c < CC; c++) s += We[d * HC + h * CC + c] * ae[h * CC + c];
        g_v[d * HEADS + h] = s;
    }
}

// ---------------- GEMM x = z @ W, fused alpha_src/alpha_dst ----------------
// block = 256 threads = 8 warps = 8 nodes; W staged in dynamic smem (64KB)
__global__ void __launch_bounds__(256) k_gemm(
    const float* __restrict__ z, const float* __restrict__ W,
    const float* __restrict__ a_src, const float* __restrict__ a_dst)
{
    extern __shared__ float sm[];
    float* Ws = sm;                 // HID*HC floats
    float* zs = sm + HID * HC;      // 8*HID floats
    int tid = threadIdx.x;
    int node0 = blockIdx.x * 8;

    float4* Ws4 = (float4*)Ws;
    const float4* Wg4 = (const float4*)W;
    #pragma unroll 4
    for (int i = tid; i < HID * HC / 4; i += 256) Ws4[i] = Wg4[i];
    for (int i = tid; i < 8 * HID; i += 256) zs[i] = z[node0 * HID + i];
    __syncthreads();

    int w = tid >> 5, l = tid & 31;
    int n = node0 + w;

    float zr[HID];
    #pragma unroll
    for (int k = 0; k < HID; k++) zr[k] = zs[w * HID + k];

    float acc[8];
    #pragma unroll
    for (int j = 0; j < 8; j++) acc[j] = 0.f;

    // thread l handles cols [l*4 .. l*4+3] (acc 0-3) and [128 + l*4 ..] (acc 4-7)
    #pragma unroll
    for (int k = 0; k < HID; k++) {
        float4 wa = Ws4[k * 64 + l];        // conflict-free: 16B stride across lanes
        float4 wb = Ws4[k * 64 + 32 + l];
        float zk = zr[k];
        acc[0] = fmaf(zk, wa.x, acc[0]);
        acc[1] = fmaf(zk, wa.y, acc[1]);
        acc[2] = fmaf(zk, wa.z, acc[2]);
        acc[3] = fmaf(zk, wa.w, acc[3]);
        acc[4] = fmaf(zk, wb.x, acc[4]);
        acc[5] = fmaf(zk, wb.y, acc[5]);
        acc[6] = fmaf(zk, wb.z, acc[6]);
        acc[7] = fmaf(zk, wb.w, acc[7]);
    }

    float4* xg = (float4*)(g_x + (size_t)n * HC);
    xg[l]      = make_float4(acc[0], acc[1], acc[2], acc[3]);
    xg[32 + l] = make_float4(acc[4], acc[5], acc[6], acc[7]);

    // fused attention-logit dot products:
    // lanes 0-15 cover head hA=0 (cols 0..63) via acc[0..3] and head 2 via acc[4..7]
    // lanes 16-31 cover head 1 and head 3
    int hA = l >> 4;
    int hB = 2 + hA;
    int co = (l & 15) * 4;
    float sA = 0.f, sB = 0.f, dA = 0.f, dB = 0.f;
    #pragma unroll
    for (int j = 0; j < 4; j++) {
        sA = fmaf(acc[j],     a_src[hA * CC + co + j], sA);
        dA = fmaf(acc[j],     a_dst[hA * CC + co + j], dA);
        sB = fmaf(acc[4 + j], a_src[hB * CC + co + j], sB);
        dB = fmaf(acc[4 + j], a_dst[hB * CC + co + j], dB);
    }
    #pragma unroll
    for (int off = 8; off; off >>= 1) {
        sA += __shfl_down_sync(0xFFFFFFFFu, sA, off, 16);
        sB += __shfl_down_sync(0xFFFFFFFFu, sB, off, 16);
        dA += __shfl_down_sync(0xFFFFFFFFu, dA, off, 16);
        dB += __shfl_down_sync(0xFFFFFFFFu, dB, off, 16);
    }
    if (l == 0) {
        g_as[n * 4 + 0] = sA; g_as[n * 4 + 2] = sB;
        g_ad[n * 4 + 0] = dA; g_ad[n * 4 + 2] = dB;
    } else if (l == 16) {
        g_as[n * 4 + 1] = sA; g_as[n * 4 + 3] = sB;
        g_ad[n * 4 + 1] = dA; g_ad[n * 4 + 3] = dB;
    }
}

// ---------------- per-edge logits + segment max ----------------
__global__ void k_logit(const int* __restrict__ src, const int* __restrict__ dst,
                        const float* __restrict__ ea)
{
    int e = blockIdx.x * 256 + threadIdx.x;
    if (e >= EE) return;
    int s = src[e], d = dst[e];
    float e0 = ea[e * 3 + 0], e1 = ea[e * 3 + 1], e2 = ea[e * 3 + 2];
    float4 as4 = ((const float4*)g_as)[s];
    float4 ad4 = ((const float4*)g_ad)[d];
    const float* av = (const float*)&as4;
    const float* dv = (const float*)&ad4;
    float lg[4];
    #pragma unroll
    for (int h = 0; h < 4; h++) {
        float aeh = e0 * g_v[0 * 4 + h] + e1 * g_v[1 * 4 + h] + e2 * g_v[2 * 4 + h];
        float x = av[h] + dv[h] + aeh;
        x = (x > 0.f) ? x : 0.2f * x;   // leaky_relu(0.2)
        lg[h] = x;
        atomicMax(&g_maxkey[d * 4 + h], fenc(x));
    }
    ((float4*)g_ex)[e] = make_float4(lg[0], lg[1], lg[2], lg[3]);
}

// ---------------- exp(logit - max), segment sum ----------------
__global__ void k_exp(const int* __restrict__ dst) {
    int e = blockIdx.x * 256 + threadIdx.x;
    if (e >= EE) return;
    int d = dst[e];
    float4 lg = ((const float4*)g_ex)[e];
    uint4 mk = ((const uint4*)g_maxkey)[d];
    float ex0 = expf(lg.x - fdec(mk.x));
    float ex1 = expf(lg.y - fdec(mk.y));
    float ex2 = expf(lg.z - fdec(mk.z));
    float ex3 = expf(lg.w - fdec(mk.w));
    ((float4*)g_ex)[e] = make_float4(ex0, ex1, ex2, ex3);
    atomicAdd(&g_denom[d * 4 + 0], ex0);
    atomicAdd(&g_denom[d * 4 + 1], ex1);
    atomicAdd(&g_denom[d * 4 + 2], ex2);
    atomicAdd(&g_denom[d * 4 + 3], ex3);
}

// ---------------- message: head-combine then scatter-add ----------------
// one warp per edge; lane handles cols l and l+32
__global__ void k_msg(const int* __restrict__ src, const int* __restrict__ dst) {
    int e = (blockIdx.x * 256 + threadIdx.x) >> 5;
    int l = threadIdx.x & 31;
    if (e >= EE) return;
    int s = src[e], d = dst[e];
    float4 ex4 = ((const float4*)g_ex)[e];
    float4 dn4 = ((const float4*)g_denom)[d];
    float al[4];
    al[0] = ex4.x / (dn4.x + 1e-16f) * 0.25f;   // 0.25 = head mean
    al[1] = ex4.y / (dn4.y + 1e-16f) * 0.25f;
    al[2] = ex4.z / (dn4.z + 1e-16f) * 0.25f;
    al[3] = ex4.w / (dn4.w + 1e-16f) * 0.25f;
    const float* xr = g_x + (size_t)s * HC;
    float m0 = 0.f, m1 = 0.f;
    #pragma unroll
    for (int h = 0; h < 4; h++) {
        m0 = fmaf(al[h], xr[h * 64 + l],      m0);
        m1 = fmaf(al[h], xr[h * 64 + 32 + l], m1);
    }
    atomicAdd(&g_accum[d * 64 + l],      m0);
    atomicAdd(&g_accum[d * 64 + 32 + l], m1);
}

// ---------------- bias + layernorm + silu; one warp per node ----------------
__global__ void k_fin(const float* __restrict__ b, const float* __restrict__ lg,
                      const float* __restrict__ lb, float* __restrict__ out)
{
    int n = (blockIdx.x * 256 + threadIdx.x) >> 5;
    int l = threadIdx.x & 31;
    if (n >= NN) return;
    float v0 = g_accum[n * 64 + l]      + b[l];
    float v1 = g_accum[n * 64 + 32 + l] + b[32 + l];
    float s = v0 + v1;
    #pragma unroll
    for (int off = 16; off; off >>= 1) s += __shfl_xor_sync(0xFFFFFFFFu, s, off);
    float mu = s * (1.0f / 64.0f);
    float q = (v0 - mu) * (v0 - mu) + (v1 - mu) * (v1 - mu);
    #pragma unroll
    for (int off = 16; off; off >>= 1) q += __shfl_xor_sync(0xFFFFFFFFu, q, off);
    float r = rsqrtf(q * (1.0f / 64.0f) + 1e-5f);
    float y0 = (v0 - mu) * r * lg[l]      + lb[l];
    float y1 = (v1 - mu) * r * lg[32 + l] + lb[32 + l];
    y0 = y0 / (1.0f + expf(-y0));   // silu
    y1 = y1 / (1.0f + expf(-y1));
    out[n * 64 + l]      = y0;
    out[n * 64 + 32 + l] = y1;
}

// ---------------- launch ----------------
extern "C" void kernel_launch(void* const* d_in, const int* in_sizes, int n_in,
                              void* d_out, int out_size)
{
    const float* h   = (const float*)d_in[1];
    const int*   ei  = (const int*)d_in[2];
    const float* ea  = (const float*)d_in[3];
    const int*   src = ei;
    const int*   dst = ei + EE;

    const float* W[2]   = { (const float*)d_in[4],  (const float*)d_in[12] };
    const float* We[2]  = { (const float*)d_in[5],  (const float*)d_in[13] };
    const float* asr[2] = { (const float*)d_in[6],  (const float*)d_in[14] };
    const float* ads[2] = { (const float*)d_in[7],  (const float*)d_in[15] };
    const float* aeg[2] = { (const float*)d_in[8],  (const float*)d_in[16] };
    const float* bb[2]  = { (const float*)d_in[9],  (const float*)d_in[17] };
    const float* lng[2] = { (const float*)d_in[10], (const float*)d_in[18] };
    const float* lnb[2] = { (const float*)d_in[11], (const float*)d_in[19] };

    const int smem = (HID * HC + 8 * HID) * (int)sizeof(float);  // 67584 B
    cudaFuncSetAttribute(k_gemm, cudaFuncAttributeMaxDynamicSharedMemorySize, smem);

    float* zbuf = nullptr;
    cudaGetSymbolAddress((void**)&zbuf, g_z);

    const float* zin = h;
    for (int L = 0; L < 2; L++) {
        float* zout = (L == 0) ? zbuf : (float*)d_out;
        k_init <<< (NN * CC + 255) / 256, 256 >>> ();
        k_v    <<< 1, 32 >>> (We[L], aeg[L]);
        k_gemm <<< NN / 8, 256, smem >>> (zin, W[L], asr[L], ads[L]);
        k_logit<<< EE / 256, 256 >>> (src, dst, ea);
        k_exp  <<< EE / 256, 256 >>> (dst);
        k_msg  <<< EE / 8, 256 >>> (src, dst);
        k_fin  <<< NN / 8, 256 >>> (bb[L], lng[L], lnb[L], zout);
        zin = zbuf;
    }
}

// round 4
// speedup vs baseline: 2.2250x; 2.2250x over previous
#include <cuda_runtime.h>
#include <cuda_fp16.h>
#include <math.h>

#define NN    32768
#define EE    262144
#define HID   64
#define HEADS 4
#define CC    64
#define HC    256
#define EDIM  3

// ---------------- scratch ----------------
__device__ __half  g_xh[(size_t)NN * HC];      // projected features, fp16 [N, H*C]
__device__ float   g_as[NN * HEADS];
__device__ float   g_ad[NN * HEADS];
__device__ float   g_ex[(size_t)EE * HEADS];   // exp(logit)
__device__ float   g_denom[NN * HEADS];
__device__ float   g_accum[(size_t)NN * CC];
__device__ float   g_z[(size_t)NN * HID];
__device__ float   g_v[2 * EDIM * HEADS];      // both layers

// ---------------- f32x2 helpers ----------------
__device__ __forceinline__ unsigned long long splat2(float x) {
    unsigned long long r; unsigned u = __float_as_uint(x);
    asm("mov.b64 %0, {%1, %2};" : "=l"(r) : "r"(u), "r"(u));
    return r;
}
__device__ __forceinline__ void ffma2(unsigned long long& d, unsigned long long a, unsigned long long b) {
    asm("fma.rn.f32x2 %0, %1, %2, %3;" : "=l"(d) : "l"(a), "l"(b), "l"(d));
}
__device__ __forceinline__ void unpack2(unsigned long long v, float& lo, float& hi) {
    unsigned a, b;
    asm("mov.b64 {%0, %1}, %2;" : "=r"(a), "=r"(b) : "l"(v));
    lo = __uint_as_float(a); hi = __uint_as_float(b);
}
__device__ __forceinline__ void red_v2(float* p, float a, float b) {
    asm volatile("red.global.add.v2.f32 [%0], {%1, %2};" :: "l"(p), "f"(a), "f"(b) : "memory");
}
__device__ __forceinline__ void red_v4(float* p, float a, float b, float c, float d) {
    asm volatile("red.global.add.v4.f32 [%0], {%1, %2, %3, %4};"
                 :: "l"(p), "f"(a), "f"(b), "f"(c), "f"(d) : "memory");
}

// ---------------- init: zero accumulators + compute g_v for both layers ----------------
__global__ void k_init(const float* __restrict__ We1, const float* __restrict__ ae1,
                       const float* __restrict__ We2, const float* __restrict__ ae2)
{
    int i = blockIdx.x * 256 + threadIdx.x;
    if (i < NN * HEADS) g_denom[i] = 0.0f;
    g_accum[i] = 0.0f;   // grid covers NN*CC exactly
    if (blockIdx.x == 0 && threadIdx.x < 2 * EDIM * HEADS) {
        int t = threadIdx.x;
        int L = t / (EDIM * HEADS);
        int r = t % (EDIM * HEADS);
        int d = r / HEADS, hh = r % HEADS;
        const float* We = L ? We2 : We1;
        const float* ae = L ? ae2 : ae1;
        float s = 0.f;
        for (int c = 0; c < CC; c++) s += We[d * HC + hh * CC + c] * ae[hh * CC + c];
        g_v[t] = s;
    }
}

// ---------------- GEMM: x = z @ W (f32x2), fused alpha dots, fp16 output ----------------
// block = 256 thr (8 warps), 64 nodes/block (8 per warp), grid = 512
// smem: W [64][256] f32 (64KB) + z [64][64] f32 (16KB)
__global__ void __launch_bounds__(256, 2) k_gemm(
    const float* __restrict__ z, const float* __restrict__ W,
    const float* __restrict__ a_src, const float* __restrict__ a_dst)
{
    extern __shared__ float sm[];
    float* Ws = sm;               // 16384 floats
    float* zs = sm + HID * HC;    // 4096 floats
    int tid = threadIdx.x;
    int node0 = blockIdx.x * 64;

    {
        float4* d4 = (float4*)Ws;
        const float4* s4 = (const float4*)W;
        #pragma unroll
        for (int i = 0; i < 16; i++) d4[tid + i * 256] = s4[tid + i * 256];
        float4* z4 = (float4*)zs;
        const float4* zg4 = (const float4*)(z + (size_t)node0 * HID);
        #pragma unroll
        for (int i = 0; i < 4; i++) z4[tid + i * 256] = zg4[tid + i * 256];
    }
    __syncthreads();

    int w = tid >> 5, l = tid & 31;
    int nbase = node0 + w * 8;

    // lane l, group g (=head g): cols {64g+2l, 64g+2l+1}
    unsigned long long acc[8][4];
    #pragma unroll
    for (int i = 0; i < 8; i++)
        #pragma unroll
        for (int g = 0; g < 4; g++) acc[i][g] = 0ull;

    const unsigned long long* Ws8 = (const unsigned long long*)Ws;

    #pragma unroll 1
    for (int k0 = 0; k0 < HID; k0 += 4) {
        float4 zb[8];
        #pragma unroll
        for (int i = 0; i < 8; i++)
            zb[i] = ((const float4*)(zs + (w * 8 + i) * HID))[k0 >> 2];
        #pragma unroll
        for (int kk = 0; kk < 4; kk++) {
            unsigned long long w0 = Ws8[(k0 + kk) * 128 + l];
            unsigned long long w1 = Ws8[(k0 + kk) * 128 + 32 + l];
            unsigned long long w2 = Ws8[(k0 + kk) * 128 + 64 + l];
            unsigned long long w3 = Ws8[(k0 + kk) * 128 + 96 + l];
            #pragma unroll
            for (int i = 0; i < 8; i++) {
                float zk = (kk == 0) ? zb[i].x : (kk == 1) ? zb[i].y : (kk == 2) ? zb[i].z : zb[i].w;
                unsigned long long z2 = splat2(zk);
                ffma2(acc[i][0], z2, w0);
                ffma2(acc[i][1], z2, w1);
                ffma2(acc[i][2], z2, w2);
                ffma2(acc[i][3], z2, w3);
            }
        }
    }

    // attention vectors: float2 at a_src[g*64 + 2l]
    float2 asv[4], adv[4];
    #pragma unroll
    for (int g = 0; g < 4; g++) {
        asv[g] = ((const float2*)a_src)[g * 32 + l];
        adv[g] = ((const float2*)a_dst)[g * 32 + l];
    }

    #pragma unroll
    for (int i = 0; i < 8; i++) {
        int n = nbase + i;
        float ps[4], pd[4];
        __half2* xo = (__half2*)(g_xh + (size_t)n * HC);
        #pragma unroll
        for (int g = 0; g < 4; g++) {
            float f0, f1;
            unpack2(acc[i][g], f0, f1);
            xo[g * 32 + l] = __floats2half2_rn(f0, f1);
            ps[g] = f0 * asv[g].x + f1 * asv[g].y;
            pd[g] = f0 * adv[g].x + f1 * adv[g].y;
        }
        #pragma unroll
        for (int off = 16; off; off >>= 1) {
            #pragma unroll
            for (int g = 0; g < 4; g++) {
                ps[g] += __shfl_xor_sync(0xFFFFFFFFu, ps[g], off);
                pd[g] += __shfl_xor_sync(0xFFFFFFFFu, pd[g], off);
            }
        }
        if (l == 0) {
            ((float4*)g_as)[n] = make_float4(ps[0], ps[1], ps[2], ps[3]);
            ((float4*)g_ad)[n] = make_float4(pd[0], pd[1], pd[2], pd[3]);
        }
    }
}

// ---------------- fused edge pass: logit -> exp -> denom (no segment max) ----------------
__global__ void k_edge(const int* __restrict__ src, const int* __restrict__ dst,
                       const float* __restrict__ ea, int L)
{
    int e = blockIdx.x * 256 + threadIdx.x;
    if (e >= EE) return;
    int s = src[e], d = dst[e];
    float e0 = ea[e * 3 + 0], e1 = ea[e * 3 + 1], e2 = ea[e * 3 + 2];
    const float* v = g_v + L * EDIM * HEADS;
    float4 as4 = ((const float4*)g_as)[s];
    float4 ad4 = ((const float4*)g_ad)[d];
    const float* av = (const float*)&as4;
    const float* dv = (const float*)&ad4;
    float ex[4];
    #pragma unroll
    for (int h = 0; h < 4; h++) {
        float x = av[h] + dv[h] + e0 * v[h] + e1 * v[4 + h] + e2 * v[8 + h];
        x = (x > 0.f) ? x : 0.2f * x;
        ex[h] = __expf(x);
    }
    ((float4*)g_ex)[e] = make_float4(ex[0], ex[1], ex[2], ex[3]);
    red_v4(&g_denom[d * 4], ex[0], ex[1], ex[2], ex[3]);
}

// ---------------- message: head-combine + scatter (fp16 gather, v2 atomics) ----------------
__global__ void k_msg(const int* __restrict__ src, const int* __restrict__ dst) {
    int e = (blockIdx.x * 256 + threadIdx.x) >> 5;
    int l = threadIdx.x & 31;
    if (e >= EE) return;
    int s = src[e], d = dst[e];
    float4 ex4 = ((const float4*)g_ex)[e];
    float4 dn4 = ((const float4*)g_denom)[d];
    float al0 = ex4.x * 0.25f * __fdividef(1.f, dn4.x + 1e-16f);
    float al1 = ex4.y * 0.25f * __fdividef(1.f, dn4.y + 1e-16f);
    float al2 = ex4.z * 0.25f * __fdividef(1.f, dn4.z + 1e-16f);
    float al3 = ex4.w * 0.25f * __fdividef(1.f, dn4.w + 1e-16f);
    const __half2* xr = (const __half2*)(g_xh + (size_t)s * HC);
    float2 f0 = __half22float2(xr[0 * 32 + l]);
    float2 f1 = __half22float2(xr[1 * 32 + l]);
    float2 f2 = __half22float2(xr[2 * 32 + l]);
    float2 f3 = __half22float2(xr[3 * 32 + l]);
    float mx = al0 * f0.x + al1 * f1.x + al2 * f2.x + al3 * f3.x;
    float my = al0 * f0.y + al1 * f1.y + al2 * f2.y + al3 * f3.y;
    red_v2(&g_accum[d * 64 + 2 * l], mx, my);
}

// ---------------- bias + layernorm + silu + zero-for-next-layer ----------------
__global__ void k_fin(const float* __restrict__ b, const float* __restrict__ lg,
                      const float* __restrict__ lb, float* __restrict__ out)
{
    int n = (blockIdx.x * 256 + threadIdx.x) >> 5;
    int l = threadIdx.x & 31;
    if (n >= NN) return;
    float v0 = g_accum[n * 64 + l]      + b[l];
    float v1 = g_accum[n * 64 + 32 + l] + b[32 + l];
    g_accum[n * 64 + l]      = 0.0f;
    g_accum[n * 64 + 32 + l] = 0.0f;
    if (l < 4) g_denom[n * 4 + l] = 0.0f;
    float s = v0 + v1;
    #pragma unroll
    for (int off = 16; off; off >>= 1) s += __shfl_xor_sync(0xFFFFFFFFu, s, off);
    float mu = s * (1.0f / 64.0f);
    float q = (v0 - mu) * (v0 - mu) + (v1 - mu) * (v1 - mu);
    #pragma unroll
    for (int off = 16; off; off >>= 1) q += __shfl_xor_sync(0xFFFFFFFFu, q, off);
    float r = rsqrtf(q * (1.0f / 64.0f) + 1e-5f);
    float y0 = (v0 - mu) * r * lg[l]      + lb[l];
    float y1 = (v1 - mu) * r * lg[32 + l] + lb[32 + l];
    y0 = y0 * __fdividef(1.0f, 1.0f + __expf(-y0));
    y1 = y1 * __fdividef(1.0f, 1.0f + __expf(-y1));
    out[n * 64 + l]      = y0;
    out[n * 64 + 32 + l] = y1;
}

// ---------------- launch ----------------
extern "C" void kernel_launch(void* const* d_in, const int* in_sizes, int n_in,
                              void* d_out, int out_size)
{
    const float* h   = (const float*)d_in[1];
    const int*   ei  = (const int*)d_in[2];
    const float* ea  = (const float*)d_in[3];
    const int*   src = ei;
    const int*   dst = ei + EE;

    const float* W[2]   = { (const float*)d_in[4],  (const float*)d_in[12] };
    const float* We[2]  = { (const float*)d_in[5],  (const float*)d_in[13] };
    const float* asr[2] = { (const float*)d_in[6],  (const float*)d_in[14] };
    const float* ads[2] = { (const float*)d_in[7],  (const float*)d_in[15] };
    const float* aeg[2] = { (const float*)d_in[8],  (const float*)d_in[16] };
    const float* bb[2]  = { (const float*)d_in[9],  (const float*)d_in[17] };
    const float* lng[2] = { (const float*)d_in[10], (const float*)d_in[18] };
    const float* lnb[2] = { (const float*)d_in[11], (const float*)d_in[19] };

    const int smem = (HID * HC + 64 * HID) * (int)sizeof(float);  // 81920 B
    cudaFuncSetAttribute(k_gemm, cudaFuncAttributeMaxDynamicSharedMemorySize, smem);

    float* zbuf = nullptr;
    cudaGetSymbolAddress((void**)&zbuf, g_z);

    k_init<<< NN * CC / 256, 256 >>>(We[0], aeg[0], We[1], aeg[1]);

    const float* zin = h;
    for (int L = 0; L < 2; L++) {
        float* zout = (L == 0) ? zbuf : (float*)d_out;
        k_gemm<<< NN / 64, 256, smem >>>(zin, W[L], asr[L], ads[L]);
        k_edge<<< EE / 256, 256 >>>(src, dst, ea, L);
        k_msg <<< EE / 8, 256 >>>(src, dst);
        k_fin <<< NN / 8, 256 >>>(bb[L], lng[L], lnb[L], zout);
        zin = zbuf;
    }
}

// round 6
// speedup vs baseline: 2.4028x; 1.0799x over previous
#include <cuda_runtime.h>
#include <cuda_fp16.h>
#include <math.h>

#define NN    32768
#define EE    262144
#define HID   64
#define HEADS 4
#define CC    64
#define HC    256
#define EDIM  3

// ---------------- scratch ----------------
// g_xh layout: per node, 32 colpairs x 4 heads x half2  => uint4 per colpair
// word h of uint4[c2] = half2( x[h, 2*c2], x[h, 2*c2+1] )
__device__ __half  g_xh[(size_t)NN * HC];
__device__ float   g_as[NN * HEADS];
__device__ float   g_ad[NN * HEADS];
__device__ float   g_ex[(size_t)EE * HEADS];   // exp(logit)
__device__ float   g_denom[NN * HEADS];
__device__ float   g_rdn[NN * HEADS];          // 0.25 / (denom + eps)
__device__ float   g_accum[(size_t)NN * CC];
__device__ float   g_z[(size_t)NN * HID];
__device__ float   g_v[2 * EDIM * HEADS];

// ---------------- f32x2 helpers ----------------
__device__ __forceinline__ unsigned long long splat2(float x) {
    unsigned long long r; unsigned u = __float_as_uint(x);
    asm("mov.b64 %0, {%1, %2};" : "=l"(r) : "r"(u), "r"(u));
    return r;
}
__device__ __forceinline__ void ffma2(unsigned long long& d, unsigned long long a, unsigned long long b) {
    asm("fma.rn.f32x2 %0, %1, %2, %3;" : "=l"(d) : "l"(a), "l"(b), "l"(d));
}
__device__ __forceinline__ void unpack2(unsigned long long v, float& lo, float& hi) {
    unsigned a, b;
    asm("mov.b64 {%0, %1}, %2;" : "=r"(a), "=r"(b) : "l"(v));
    lo = __uint_as_float(a); hi = __uint_as_float(b);
}
__device__ __forceinline__ unsigned long long pack2(float lo, float hi) {
    unsigned long long r;
    asm("mov.b64 %0, {%1, %2};" : "=l"(r) : "r"(__float_as_uint(lo)), "r"(__float_as_uint(hi)));
    return r;
}
__device__ __forceinline__ void red_v4(float* p, float a, float b, float c, float d) {
    asm volatile("red.global.add.v4.f32 [%0], {%1, %2, %3, %4};"
                 :: "l"(p), "f"(a), "f"(b), "f"(c), "f"(d) : "memory");
}

// ---------------- init: zero accumulators + compute g_v for both layers ----------------
__global__ void k_init(const float* __restrict__ We1, const float* __restrict__ ae1,
                       const float* __restrict__ We2, const float* __restrict__ ae2)
{
    int i = blockIdx.x * 256 + threadIdx.x;
    if (i < NN * HEADS) g_denom[i] = 0.0f;
    g_accum[i] = 0.0f;
    if (blockIdx.x == 0 && threadIdx.x < 2 * EDIM * HEADS) {
        int t = threadIdx.x;
        int L = t / (EDIM * HEADS);
        int r = t % (EDIM * HEADS);
        int d = r / HEADS, hh = r % HEADS;
        const float* We = L ? We2 : We1;
        const float* ae = L ? ae2 : ae1;
        float s = 0.f;
        for (int c = 0; c < CC; c++) s += We[d * HC + hh * CC + c] * ae[hh * CC + c];
        g_v[t] = s;
    }
}

// ---------------- GEMM: x = z @ W (f32x2), fused alpha dots, fp16 transposed out ----------------
__global__ void __launch_bounds__(256, 2) k_gemm(
    const float* __restrict__ z, const float* __restrict__ W,
    const float* __restrict__ a_src, const float* __restrict__ a_dst)
{
    extern __shared__ float sm[];
    float* Ws = sm;               // 16384 floats
    float* zs = sm + HID * HC;    // 4096 floats
    int tid = threadIdx.x;
    int node0 = blockIdx.x * 64;

    {
        float4* d4 = (float4*)Ws;
        const float4* s4 = (const float4*)W;
        #pragma unroll
        for (int i = 0; i < 16; i++) d4[tid + i * 256] = s4[tid + i * 256];
        float4* z4 = (float4*)zs;
        const float4* zg4 = (const float4*)(z + (size_t)node0 * HID);
        #pragma unroll
        for (int i = 0; i < 4; i++) z4[tid + i * 256] = zg4[tid + i * 256];
    }
    __syncthreads();

    int w = tid >> 5, l = tid & 31;
    int nbase = node0 + w * 8;

    // lane l, head g: cols {64g+2l, 64g+2l+1}
    unsigned long long acc[8][4];
    #pragma unroll
    for (int i = 0; i < 8; i++)
        #pragma unroll
        for (int g = 0; g < 4; g++) acc[i][g] = 0ull;

    const unsigned long long* Ws8 = (const unsigned long long*)Ws;

    #pragma unroll 1
    for (int k0 = 0; k0 < HID; k0 += 4) {
        float4 zb[8];
        #pragma unroll
        for (int i = 0; i < 8; i++)
            zb[i] = ((const float4*)(zs + (w * 8 + i) * HID))[k0 >> 2];
        #pragma unroll
        for (int kk = 0; kk < 4; kk++) {
            unsigned long long w0 = Ws8[(k0 + kk) * 128 + l];
            unsigned long long w1 = Ws8[(k0 + kk) * 128 + 32 + l];
            unsigned long long w2 = Ws8[(k0 + kk) * 128 + 64 + l];
            unsigned long long w3 = Ws8[(k0 + kk) * 128 + 96 + l];
            #pragma unroll
            for (int i = 0; i < 8; i++) {
                float zk = (kk == 0) ? zb[i].x : (kk == 1) ? zb[i].y : (kk == 2) ? zb[i].z : zb[i].w;
                unsigned long long z2 = splat2(zk);
                ffma2(acc[i][0], z2, w0);
                ffma2(acc[i][1], z2, w1);
                ffma2(acc[i][2], z2, w2);
                ffma2(acc[i][3], z2, w3);
            }
        }
    }

    float2 asv[4], adv[4];
    #pragma unroll
    for (int g = 0; g < 4; g++) {
        asv[g] = ((const float2*)a_src)[g * 32 + l];
        adv[g] = ((const float2*)a_dst)[g * 32 + l];
    }

    #pragma unroll
    for (int i = 0; i < 8; i++) {
        int n = nbase + i;
        float ps[4], pd[4];
        unsigned xw[4];
        #pragma unroll
        for (int g = 0; g < 4; g++) {
            float f0, f1;
            unpack2(acc[i][g], f0, f1);
            __half2 h2 = __floats2half2_rn(f0, f1);
            xw[g] = *(unsigned*)&h2;
            ps[g] = f0 * asv[g].x + f1 * asv[g].y;
            pd[g] = f0 * adv[g].x + f1 * adv[g].y;
        }
        // transposed store: uint4 per colpair l holds heads 0..3
        ((uint4*)(g_xh + (size_t)n * HC))[l] = make_uint4(xw[0], xw[1], xw[2], xw[3]);
        #pragma unroll
        for (int off = 16; off; off >>= 1) {
            #pragma unroll
            for (int g = 0; g < 4; g++) {
                ps[g] += __shfl_xor_sync(0xFFFFFFFFu, ps[g], off);
                pd[g] += __shfl_xor_sync(0xFFFFFFFFu, pd[g], off);
            }
        }
        if (l == 0) {
            ((float4*)g_as)[n] = make_float4(ps[0], ps[1], ps[2], ps[3]);
            ((float4*)g_ad)[n] = make_float4(pd[0], pd[1], pd[2], pd[3]);
        }
    }
}

// ---------------- fused edge pass: logit -> exp -> denom ----------------
__global__ void k_edge(const int* __restrict__ src, const int* __restrict__ dst,
                       const float* __restrict__ ea, int L)
{
    int e = blockIdx.x * 256 + threadIdx.x;
    if (e >= EE) return;
    int s = src[e], d = dst[e];
    float e0 = ea[e * 3 + 0], e1 = ea[e * 3 + 1], e2 = ea[e * 3 + 2];
    const float* v = g_v + L * EDIM * HEADS;
    float4 as4 = ((const float4*)g_as)[s];
    float4 ad4 = ((const float4*)g_ad)[d];
    const float* av = (const float*)&as4;
    const float* dv = (const float*)&ad4;
    float ex[4];
    #pragma unroll
    for (int h = 0; h < 4; h++) {
        float x = av[h] + dv[h] + e0 * v[h] + e1 * v[4 + h] + e2 * v[8 + h];
        x = (x > 0.f) ? x : 0.2f * x;
        ex[h] = __expf(x);
    }
    ((float4*)g_ex)[e] = make_float4(ex[0], ex[1], ex[2], ex[3]);
    red_v4(&g_denom[d * 4], ex[0], ex[1], ex[2], ex[3]);
}

// ---------------- reciprocal denom (with head-mean 0.25 folded in) ----------------
__global__ void k_rcp() {
    int i = blockIdx.x * 256 + threadIdx.x;   // NN*HEADS threads
    float dn = g_denom[i];
    g_rdn[i] = 0.25f * __fdividef(1.0f, dn + 1e-16f);
    g_denom[i] = 0.0f;   // ready for next layer
}

// ---------------- message: 2 edges/warp, 16 lanes/edge, red.v4 ----------------
// grid covers EE/2 warps -> EE/16 blocks of 8 warps
__global__ void k_msg(const int* __restrict__ src, const int* __restrict__ dst) {
    int t = blockIdx.x * 256 + threadIdx.x;
    int lane = threadIdx.x & 31;
    int e = ((t >> 5) << 1) + (lane >> 4);    // 2 edges per warp
    int r = lane & 15;                        // lane within edge: cols 4r..4r+3
    int s = src[e], d = dst[e];
    float4 ex4 = ((const float4*)g_ex)[e];
    float4 rd4 = ((const float4*)g_rdn)[d];
    float al0 = ex4.x * rd4.x;
    float al1 = ex4.y * rd4.y;
    float al2 = ex4.z * rd4.z;
    float al3 = ex4.w * rd4.w;

    const uint4* xr = (const uint4*)(g_xh + (size_t)s * HC);
    uint4 a = xr[2 * r];       // colpair 2r : heads 0..3
    uint4 b = xr[2 * r + 1];   // colpair 2r+1

    unsigned long long A0 = splat2(al0), A1 = splat2(al1), A2 = splat2(al2), A3 = splat2(al3);

    float2 f; unsigned long long pa = 0ull, pb = 0ull;
    f = __half22float2(*(__half2*)&a.x); ffma2(pa, A0, pack2(f.x, f.y));
    f = __half22float2(*(__half2*)&a.y); ffma2(pa, A1, pack2(f.x, f.y));
    f = __half22float2(*(__half2*)&a.z); ffma2(pa, A2, pack2(f.x, f.y));
    f = __half22float2(*(__half2*)&a.w); ffma2(pa, A3, pack2(f.x, f.y));
    f = __half22float2(*(__half2*)&b.x); ffma2(pb, A0, pack2(f.x, f.y));
    f = __half22float2(*(__half2*)&b.y); ffma2(pb, A1, pack2(f.x, f.y));
    f = __half22float2(*(__half2*)&b.z); ffma2(pb, A2, pack2(f.x, f.y));
    f = __half22float2(*(__half2*)&b.w); ffma2(pb, A3, pack2(f.x, f.y));

    float m0, m1, m2, m3;
    unpack2(pa, m0, m1);
    unpack2(pb, m2, m3);
    red_v4(&g_accum[d * 64 + 4 * r], m0, m1, m2, m3);
}

// ---------------- bias + layernorm + silu + zero-for-next-layer ----------------
__global__ void k_fin(const float* __restrict__ b, const float* __restrict__ lg,
                      const float* __restrict__ lb, float* __restrict__ out)
{
    int n = (blockIdx.x * 256 + threadIdx.x) >> 5;
    int l = threadIdx.x & 31;
    if (n >= NN) return;
    float v0 = g_accum[n * 64 + l]      + b[l];
    float v1 = g_accum[n * 64 + 32 + l] + b[32 + l];
    g_accum[n * 64 + l]      = 0.0f;
    g_accum[n * 64 + 32 + l] = 0.0f;
    float s = v0 + v1;
    #pragma unroll
    for (int off = 16; off; off >>= 1) s += __shfl_xor_sync(0xFFFFFFFFu, s, off);
    float mu = s * (1.0f / 64.0f);
    float q = (v0 - mu) * (v0 - mu) + (v1 - mu) * (v1 - mu);
    #pragma unroll
    for (int off = 16; off; off >>= 1) q += __shfl_xor_sync(0xFFFFFFFFu, q, off);
    float r = rsqrtf(q * (1.0f / 64.0f) + 1e-5f);
    float y0 = (v0 - mu) * r * lg[l]      + lb[l];
    float y1 = (v1 - mu) * r * lg[32 + l] + lb[32 + l];
    y0 = y0 * __fdividef(1.0f, 1.0f + __expf(-y0));
    y1 = y1 * __fdividef(1.0f, 1.0f + __expf(-y1));
    out[n * 64 + l]      = y0;
    out[n * 64 + 32 + l] = y1;
}

// ---------------- launch ----------------
extern "C" void kernel_launch(void* const* d_in, const int* in_sizes, int n_in,
                              void* d_out, int out_size)
{
    const float* h   = (const float*)d_in[1];
    const int*   ei  = (const int*)d_in[2];
    const float* ea  = (const float*)d_in[3];
    const int*   src = ei;
    const int*   dst = ei + EE;

    const float* W[2]   = { (const float*)d_in[4],  (const float*)d_in[12] };
    const float* We[2]  = { (const float*)d_in[5],  (const float*)d_in[13] };
    const float* asr[2] = { (const float*)d_in[6],  (const float*)d_in[14] };
    const float* ads[2] = { (const float*)d_in[7],  (const float*)d_in[15] };
    const float* aeg[2] = { (const float*)d_in[8],  (const float*)d_in[16] };
    const float* bb[2]  = { (const float*)d_in[9],  (const float*)d_in[17] };
    const float* lng[2] = { (const float*)d_in[10], (const float*)d_in[18] };
    const float* lnb[2] = { (const float*)d_in[11], (const float*)d_in[19] };

    const int smem = (HID * HC + 64 * HID) * (int)sizeof(float);  // 81920 B
    cudaFuncSetAttribute(k_gemm, cudaFuncAttributeMaxDynamicSharedMemorySize, smem);

    float* zbuf = nullptr;
    cudaGetSymbolAddress((void**)&zbuf, g_z);

    k_init<<< NN * CC / 256, 256 >>>(We[0], aeg[0], We[1], aeg[1]);

    const float* zin = h;
    for (int L = 0; L < 2; L++) {
        float* zout = (L == 0) ? zbuf : (float*)d_out;
        k_gemm<<< NN / 64, 256, smem >>>(zin, W[L], asr[L], ads[L]);
        k_edge<<< EE / 256, 256 >>>(src, dst, ea, L);
        k_rcp <<< NN * HEADS / 256, 256 >>>();
        k_msg <<< EE / 16, 256 >>>(src, dst);   // FIXED: 2 edges/warp -> EE/16 blocks
        k_fin <<< NN / 8, 256 >>>(bb[L], lng[L], lnb[L], zout);
        zin = zbuf;
    }
}